// round 17
// baseline (speedup 1.0000x reference)
#include <cuda_runtime.h>
#include <cstdint>
#include <cstddef>

// Problem constants
#define NB    4
#define NTOK  2048
#define CIN   1024
#define QKDIM 512
#define OUTCH 1024
#define NH    8
#define HD    64     // per-head qk dim
#define VD    128    // per-head value dim
// Q is pre-scaled by 0.125*log2(e) in the GEMM epilogue, so attention's
// softmax is exp(s*0.125) = ex2(S') with S' = Q'.K already in log2 domain.
#define SC_LOG2E 0.18033688011112042f

// Scratch (static device globals)
static __device__ float g_Q[(size_t)NB * NH * NTOK * HD];   // [bh][tok][d]  tf32, PRE-SCALED
static __device__ float g_K[(size_t)NB * NH * NTOK * HD];   // [bh][tok][d]  tf32
static __device__ float g_V[(size_t)NB * NH * NTOK * VD];   // [bh][tok][v]  tf32
static __device__ float g_Xr[(size_t)NB * NTOK * CIN];      // tf32-rounded X
static __device__ float g_Wqr[(size_t)CIN * QKDIM];
static __device__ float g_Wkr[(size_t)CIN * QKDIM];
static __device__ float g_Wvr[(size_t)CIN * OUTCH];

// ---------------------------------------------------------------- helpers
__device__ __forceinline__ uint32_t f2tf(float x) {
    uint32_t u;
    asm("cvt.rna.tf32.f32 %0, %1;" : "=r"(u) : "f"(x));
    return u;
}
__device__ __forceinline__ float tfround(float x) { return __uint_as_float(f2tf(x)); }
// What HMMA.TF32 sees when fed raw fp32 bits: mantissa truncated to 10 bits.
__device__ __forceinline__ float tftrunc(float x) {
    return __uint_as_float(__float_as_uint(x) & 0xffffe000u);
}
__device__ __forceinline__ float ex2(float x) {
    float r;
    asm("ex2.approx.f32 %0, %1;" : "=f"(r) : "f"(x));
    return r;
}
__device__ __forceinline__ void mma_tf32(float c[4], const uint32_t a[4], const uint32_t b[2]) {
    asm volatile(
        "mma.sync.aligned.m16n8k8.row.col.f32.tf32.tf32.f32 "
        "{%0,%1,%2,%3},{%4,%5,%6,%7},{%8,%9},{%0,%1,%2,%3};"
        : "+f"(c[0]), "+f"(c[1]), "+f"(c[2]), "+f"(c[3])
        : "r"(a[0]), "r"(a[1]), "r"(a[2]), "r"(a[3]), "r"(b[0]), "r"(b[1]));
}
__device__ __forceinline__ uint32_t smem_u32(const void* p) {
    return (uint32_t)__cvta_generic_to_shared(p);
}
__device__ __forceinline__ void cp16(uint32_t dst, const void* src) {
    asm volatile("cp.async.cg.shared.global [%0], [%1], 16;" :: "r"(dst), "l"(src));
}
__device__ __forceinline__ void cp_commit() { asm volatile("cp.async.commit_group;"); }

// ================================================================ Pre-round X  (launch idx 0)
#define NX4  ((NB * NTOK * CIN) / 4)
__global__ __launch_bounds__(256)
void preround_x(const float4* __restrict__ X)
{
    for (size_t i = (size_t)blockIdx.x * blockDim.x + threadIdx.x;
         i < NX4; i += (size_t)gridDim.x * blockDim.x) {
        float4 v = X[i];
        v.x = tfround(v.x); v.y = tfround(v.y); v.z = tfround(v.z); v.w = tfround(v.w);
        ((float4*)g_Xr)[i] = v;
    }
}

// ================================================================ Pre-round W  (launch idx 1)
#define NQ4  ((CIN * QKDIM) / 4)
#define NV4  ((CIN * OUTCH) / 4)
#define NW4  (2 * NQ4 + NV4)
__global__ __launch_bounds__(256)
void preround_w(const float4* __restrict__ Wq, const float4* __restrict__ Wk,
                const float4* __restrict__ Wv)
{
    for (size_t i = (size_t)blockIdx.x * blockDim.x + threadIdx.x;
         i < NW4; i += (size_t)gridDim.x * blockDim.x) {
        float4 v; float4* dst;
        if (i < NQ4)            { v = Wq[i];           dst = ((float4*)g_Wqr) + i; }
        else if (i < 2 * NQ4)   { v = Wk[i - NQ4];     dst = ((float4*)g_Wkr) + (i - NQ4); }
        else                    { v = Wv[i - 2 * NQ4]; dst = ((float4*)g_Wvr) + (i - 2 * NQ4); }
        v.x = tfround(v.x); v.y = tfround(v.y); v.z = tfround(v.z); v.w = tfround(v.w);
        *dst = v;
    }
}

// ================================================================ QKV GEMM (2 CTAs/SM, verified R15)
#define GA_PITCH 36
#define GB_PITCH 136
#define GA_STAGE (128 * GA_PITCH)
#define GB_STAGE (32 * GB_PITCH)
#define GEMM_SMEM_BYTES ((2 * GA_STAGE + 2 * GB_STAGE) * 4)

__global__ __launch_bounds__(256, 2)
void qkv_gemm(const float* __restrict__ bq, const float* __restrict__ bk,
              const float* __restrict__ bv)
{
    extern __shared__ float sm[];
    float* As = sm;
    float* Bs = sm + 2 * GA_STAGE;

    const int tid = threadIdx.x;
    const int m0 = blockIdx.y * 128;
    const int n0 = blockIdx.x * 128;

    const float* Wsrc;
    int wld, nc0;
    if (n0 < QKDIM)          { Wsrc = g_Wqr; wld = QKDIM; nc0 = n0;            }
    else if (n0 < 2 * QKDIM) { Wsrc = g_Wkr; wld = QKDIM; nc0 = n0 - QKDIM;    }
    else                     { Wsrc = g_Wvr; wld = OUTCH; nc0 = n0 - 2*QKDIM;  }

    const uint32_t as_b = smem_u32(As);
    const uint32_t bs_b = smem_u32(Bs);

    auto load_stage = [&](int stage, int k0) {
        #pragma unroll
        for (int i = 0; i < 4; i++) {
            int idx = tid + 256 * i;
            int r = idx >> 3, c4 = idx & 7;
            cp16(as_b + (uint32_t)(stage * GA_STAGE + r * GA_PITCH + c4 * 4) * 4,
                 g_Xr + (size_t)(m0 + r) * CIN + k0 + c4 * 4);
        }
        #pragma unroll
        for (int i = 0; i < 4; i++) {
            int idx = tid + 256 * i;
            int r = idx >> 5, c4 = idx & 31;
            cp16(bs_b + (uint32_t)(stage * GB_STAGE + r * GB_PITCH + c4 * 4) * 4,
                 Wsrc + (size_t)(k0 + r) * wld + nc0 + c4 * 4);
        }
        cp_commit();
    };

    const int wid = tid >> 5, lane = tid & 31;
    const int wm = wid & 3, wn = wid >> 2;
    const int g = lane >> 2, tg = lane & 3;

    float acc[2][8][4];
    #pragma unroll
    for (int mi = 0; mi < 2; mi++)
        #pragma unroll
        for (int ni = 0; ni < 8; ni++)
            #pragma unroll
            for (int j = 0; j < 4; j++) acc[mi][ni][j] = 0.f;

    load_stage(0, 0);

    const int KT = CIN / 32;
    for (int kt = 0; kt < KT; kt++) {
        if (kt + 1 < KT) {
            load_stage((kt + 1) & 1, (kt + 1) * 32);
            asm volatile("cp.async.wait_group 1;");
        } else {
            asm volatile("cp.async.wait_group 0;");
        }
        __syncthreads();

        const float* A  = As + (kt & 1) * GA_STAGE;
        const float* Bt = Bs + (kt & 1) * GB_STAGE;

        #pragma unroll
        for (int ks = 0; ks < 4; ks++) {
            uint32_t af[2][4];
            #pragma unroll
            for (int mi = 0; mi < 2; mi++) {
                int r0 = wm * 32 + mi * 16 + g;
                af[mi][0] = __float_as_uint(A[r0 * GA_PITCH + ks * 8 + tg]);
                af[mi][1] = __float_as_uint(A[(r0 + 8) * GA_PITCH + ks * 8 + tg]);
                af[mi][2] = __float_as_uint(A[r0 * GA_PITCH + ks * 8 + tg + 4]);
                af[mi][3] = __float_as_uint(A[(r0 + 8) * GA_PITCH + ks * 8 + tg + 4]);
            }
            #pragma unroll
            for (int ni = 0; ni < 8; ni++) {
                int col = wn * 64 + ni * 8 + g;
                uint32_t bf[2];
                bf[0] = __float_as_uint(Bt[(ks * 8 + tg) * GB_PITCH + col]);
                bf[1] = __float_as_uint(Bt[(ks * 8 + tg + 4) * GB_PITCH + col]);
                mma_tf32(acc[0][ni], af[0], bf);
                mma_tf32(acc[1][ni], af[1], bf);
            }
        }
        __syncthreads();
    }

    #pragma unroll
    for (int mi = 0; mi < 2; mi++) {
        #pragma unroll
        for (int ni = 0; ni < 8; ni++) {
            #pragma unroll
            for (int j = 0; j < 4; j++) {
                int r = wm * 32 + mi * 16 + g + ((j >= 2) ? 8 : 0);
                int c = wn * 64 + ni * 8 + tg * 2 + (j & 1);
                int m = m0 + r, n = n0 + c;
                int b = m >> 11, tok = m & 2047;
                float v = acc[mi][ni][j];
                if (n < QKDIM) {
                    // Q pre-scaled: S = Q'.K arrives in log2 domain for ex2.
                    v = tfround((v + bq[n]) * SC_LOG2E);
                    int h = n >> 6, d = n & 63;
                    g_Q[(((size_t)(b * NH + h)) * NTOK + tok) * HD + d] = v;
                } else if (n < 2 * QKDIM) {
                    int n2 = n - QKDIM;
                    v = tfround(v + bk[n2]);
                    int h = n2 >> 6, d = n2 & 63;
                    g_K[(((size_t)(b * NH + h)) * NTOK + tok) * HD + d] = v;
                } else {
                    int n2 = n - 2 * QKDIM;
                    v = tfround(v + bv[n2]);
                    int h = n2 >> 7, vd = n2 & 127;
                    g_V[(((size_t)(b * NH + h)) * NTOK + tok) * VD + vd] = v;
                }
            }
        }
    }
}

// ================================================================ Attention
// R16 structure (2m x 2n warps, K double-buffered, slot-ordered P + sigma V,
// own-half P@V from registers) with the pre-mid critical path cut further:
//  - Q pre-scaled in gemm -> exp is a BARE ex2 (no FMUL on the S->P chain)
//  - rsum accumulation (trunc+adds) moved AFTER the mid barrier (s regs
//    still hold the exp'd values there); pre-mid phase = ex2 + stores only.
#define QP 68     // 68 mod 32 = 4 -> Q/K/P frag reads bank 4g+tg = lane (CF)
#define VP 136    // 136 mod 32 = 8 -> V frag reads bank 8tg+g = perm(lane) (CF)
#define P_FLOATS (64 * QP)
#define K_STAGE  (64 * QP)
#define V_FLOATS (64 * VP)
#define ATT_SMEM_BYTES ((P_FLOATS + 2 * K_STAGE + V_FLOATS) * 4)   // 87040

__global__ __launch_bounds__(128, 2)
void attn_kernel(float* __restrict__ out)
{
    extern __shared__ float sm[];
    float* Ps = sm;                       // [64][QP]  (Q staging, then P slots)
    float* Ks = sm + P_FLOATS;            // [2][64][QP]
    float* Vs = Ks + 2 * K_STAGE;         // [64][VP]  rows sigma-permuted

    const int tid = threadIdx.x;
    const int qt = blockIdx.x;            // 0..31
    const int bh = blockIdx.y;            // 0..31
    const int b = bh >> 3, h = bh & 7;

    const float* Qg = g_Q + ((size_t)bh * NTOK + qt * 64) * HD;
    const float* Kg = g_K + (size_t)bh * NTOK * HD;
    const float* Vg = g_V + (size_t)bh * NTOK * VD;

    const uint32_t ps_b = smem_u32(Ps);
    const uint32_t ks_b = smem_u32(Ks);
    const uint32_t vs_b = smem_u32(Vs);

    // Stage Q into Ps                                         [group 0: Q]
    #pragma unroll
    for (int i = 0; i < 8; i++) {
        int idx = tid + 128 * i;
        int r = idx >> 4, c4 = idx & 15;
        cp16(ps_b + (uint32_t)(r * QP + c4 * 4) * 4, Qg + (size_t)r * HD + c4 * 4);
    }
    cp_commit();

    auto loadK = [&](int t) {             // into buffer t&1
        const float* Kt = Kg + (size_t)t * 64 * HD;
        uint32_t base = ks_b + (uint32_t)((t & 1) * K_STAGE) * 4;
        #pragma unroll
        for (int i = 0; i < 8; i++) {
            int idx = tid + 128 * i;
            int r = idx >> 4, c4 = idx & 15;
            cp16(base + (uint32_t)(r * QP + c4 * 4) * 4, Kt + (size_t)r * HD + c4 * 4);
        }
        cp_commit();
    };
    auto loadV = [&](int t) {
        // smem row r holds token sigma(r) of the tile (within-8 permute)
        #pragma unroll
        for (int i = 0; i < 16; i++) {
            int idx = tid + 128 * i;
            int r = idx >> 5, c4 = idx & 31;
            int tok = (r & ~7) | (((r & 3) << 1) | ((r >> 2) & 1));
            cp16(vs_b + (uint32_t)(r * VP + c4 * 4) * 4,
                 Vg + ((size_t)t * 64 + tok) * VD + c4 * 4);
        }
        cp_commit();
    };

    loadK(0);          // group 1
    loadV(0);          // group 2
    loadK(1);          // group 3

    const int wid = tid >> 5, lane = tid & 31;
    const int g = lane >> 2, tg = lane & 3;
    const int wm = wid & 1, wn = wid >> 1;
    const int r0 = wm * 32;               // warp q-row base
    const int kc = wn * 32;               // warp S key-slot base
    const int vc = wn * 64;               // warp P@V v-column base

    // Q fragments -> registers (wait Q only; K0,V0,K1 in flight)
    asm volatile("cp.async.wait_group 3;");
    __syncthreads();
    uint32_t aq[2][8][4];
    #pragma unroll
    for (int mi = 0; mi < 2; mi++) {
        int rr = r0 + mi * 16 + g;
        #pragma unroll
        for (int ks = 0; ks < 8; ks++) {
            aq[mi][ks][0] = __float_as_uint(Ps[rr * QP + ks * 8 + tg]);
            aq[mi][ks][1] = __float_as_uint(Ps[(rr + 8) * QP + ks * 8 + tg]);
            aq[mi][ks][2] = __float_as_uint(Ps[rr * QP + ks * 8 + tg + 4]);
            aq[mi][ks][3] = __float_as_uint(Ps[(rr + 8) * QP + ks * 8 + tg + 4]);
        }
    }

    float oacc[2][8][4];
    #pragma unroll
    for (int mi = 0; mi < 2; mi++)
        #pragma unroll
        for (int ni = 0; ni < 8; ni++)
            #pragma unroll
            for (int j = 0; j < 4; j++) oacc[mi][ni][j] = 0.f;
    float rs[2][2] = {{0.f, 0.f}, {0.f, 0.f}};

    const int TT = NTOK / 64;   // 32
    for (int t = 0; t < TT; t++) {
        const float* Kt = Ks + (t & 1) * K_STAGE;

        // top: K(t) landed (V(t), K(t+1) may stay pending)
        asm volatile("cp.async.wait_group 2;");
        __syncthreads();

        // ---- S' = Q' @ K^T  (pre-scaled; warp: 32 rows x 32 key-slots) ----
        float s[2][4][4];
        #pragma unroll
        for (int mi = 0; mi < 2; mi++)
            #pragma unroll
            for (int ni = 0; ni < 4; ni++)
                #pragma unroll
                for (int j = 0; j < 4; j++) s[mi][ni][j] = 0.f;

        #pragma unroll
        for (int ks = 0; ks < 8; ks++) {
            #pragma unroll
            for (int ni = 0; ni < 4; ni++) {
                uint32_t bf[2];
                bf[0] = __float_as_uint(Kt[(kc + ni * 8 + g) * QP + ks * 8 + tg]);
                bf[1] = __float_as_uint(Kt[(kc + ni * 8 + g) * QP + ks * 8 + tg + 4]);
                mma_tf32(s[0][ni], aq[0][ks], bf);
                mma_tf32(s[1][ni], aq[1][ks], bf);
            }
        }

        // ---- bare ex2 in place (s becomes P); partner copy to smem SLOTS ----
        // C-frag col 2tg -> slot tg ; col 2tg+1 -> slot tg+4.
        #pragma unroll
        for (int mi = 0; mi < 2; mi++) {
            int rr = r0 + mi * 16 + g;
            #pragma unroll
            for (int ni = 0; ni < 4; ni++) {
                float e0 = ex2(s[mi][ni][0]);
                float e1 = ex2(s[mi][ni][1]);
                float e2 = ex2(s[mi][ni][2]);
                float e3 = ex2(s[mi][ni][3]);
                s[mi][ni][0] = e0; s[mi][ni][1] = e1;
                s[mi][ni][2] = e2; s[mi][ni][3] = e3;
                Ps[rr * QP + kc + ni * 8 + tg]           = e0;   // slot tg
                Ps[rr * QP + kc + ni * 8 + tg + 4]       = e1;   // slot tg+4
                Ps[(rr + 8) * QP + kc + ni * 8 + tg]     = e2;
                Ps[(rr + 8) * QP + kc + ni * 8 + tg + 4] = e3;
            }
        }

        // mid: V(t) landed; P exchange complete
        if (t + 2 < TT) { asm volatile("cp.async.wait_group 1;"); }
        else            { asm volatile("cp.async.wait_group 0;"); }
        __syncthreads();

        // rsum accumulation moved here — off the pre-mid critical path.
        // s regs still hold the exp'd values; must see what HMMA sees.
        #pragma unroll
        for (int mi = 0; mi < 2; mi++)
            #pragma unroll
            for (int ni = 0; ni < 4; ni++) {
                rs[mi][0] += tftrunc(s[mi][ni][0]) + tftrunc(s[mi][ni][1]);
                rs[mi][1] += tftrunc(s[mi][ni][2]) + tftrunc(s[mi][ni][3]);
            }

        // ---- O += P @ V (warp: 32 rows x 64 v-cols; own half from regs) ----
        #pragma unroll
        for (int ks = 0; ks < 8; ks++) {
            uint32_t af[2][4];
            if ((ks >> 2) == wn) {
                int q = ks & 3;                       // own S ni-tile
                #pragma unroll
                for (int mi = 0; mi < 2; mi++) {
                    af[mi][0] = __float_as_uint(s[mi][q][0]);  // row rr,   k=tg
                    af[mi][1] = __float_as_uint(s[mi][q][2]);  // row rr+8, k=tg
                    af[mi][2] = __float_as_uint(s[mi][q][1]);  // row rr,   k=tg+4
                    af[mi][3] = __float_as_uint(s[mi][q][3]);  // row rr+8, k=tg+4
                }
            } else {
                #pragma unroll
                for (int mi = 0; mi < 2; mi++) {
                    int rr = r0 + mi * 16 + g;
                    af[mi][0] = __float_as_uint(Ps[rr * QP + ks * 8 + tg]);
                    af[mi][1] = __float_as_uint(Ps[(rr + 8) * QP + ks * 8 + tg]);
                    af[mi][2] = __float_as_uint(Ps[rr * QP + ks * 8 + tg + 4]);
                    af[mi][3] = __float_as_uint(Ps[(rr + 8) * QP + ks * 8 + tg + 4]);
                }
            }
            #pragma unroll
            for (int ni = 0; ni < 8; ni++) {
                uint32_t bf[2];
                bf[0] = __float_as_uint(Vs[(ks * 8 + tg) * VP + vc + ni * 8 + g]);
                bf[1] = __float_as_uint(Vs[(ks * 8 + tg + 4) * VP + vc + ni * 8 + g]);
                mma_tf32(oacc[0][ni], af[0], bf);
                mma_tf32(oacc[1][ni], af[1], bf);
            }
        }

        __syncthreads();                 // end: V + P readers done
        if (t + 1 < TT) loadV(t + 1);
        if (t + 2 < TT) loadK(t + 2);    // into buf t&1 (S(t) fenced at mid)
    }

    // ---- epilogue: row-sum reduction (intra-warp, then cross-warp via smem) ----
    #pragma unroll
    for (int mi = 0; mi < 2; mi++)
        #pragma unroll
        for (int hf = 0; hf < 2; hf++) {
            float v = rs[mi][hf];
            v += __shfl_xor_sync(0xffffffffu, v, 1);
            v += __shfl_xor_sync(0xffffffffu, v, 2);
            rs[mi][hf] = v;
        }
    float* RS = Ps;                      // Ps free after last end-sync
    if (tg == 0) {
        #pragma unroll
        for (int mi = 0; mi < 2; mi++)
            #pragma unroll
            for (int hf = 0; hf < 2; hf++)
                RS[wn * 64 + r0 + mi * 16 + hf * 8 + g] = rs[mi][hf];
    }
    __syncthreads();

    #pragma unroll
    for (int mi = 0; mi < 2; mi++) {
        int rr = r0 + mi * 16 + g;
        float inv0 = 1.f / (RS[rr] + RS[64 + rr]);
        float inv1 = 1.f / (RS[rr + 8] + RS[64 + rr + 8]);
        int tokA = qt * 64 + rr;
        float* op = out + ((size_t)b * NTOK + tokA) * OUTCH + (size_t)h * VD + vc;
        #pragma unroll
        for (int ni = 0; ni < 8; ni++) {
            int c = ni * 8 + tg * 2;
            op[c]                  = oacc[mi][ni][0] * inv0;
            op[c + 1]              = oacc[mi][ni][1] * inv0;
            op[8 * OUTCH + c]      = oacc[mi][ni][2] * inv1;
            op[8 * OUTCH + c + 1]  = oacc[mi][ni][3] * inv1;
        }
    }
}

// ================================================================ launch
extern "C" void kernel_launch(void* const* d_in, const int* in_sizes, int n_in,
                              void* d_out, int out_size)
{
    const float* x  = (const float*)d_in[0];
    const float* Wq = (const float*)d_in[1];
    const float* bq = (const float*)d_in[2];
    const float* Wk = (const float*)d_in[3];
    const float* bk = (const float*)d_in[4];
    const float* Wv = (const float*)d_in[5];
    const float* bv = (const float*)d_in[6];
    float* out = (float*)d_out;

    cudaFuncSetAttribute(qkv_gemm, cudaFuncAttributeMaxDynamicSharedMemorySize,
                         GEMM_SMEM_BYTES);
    cudaFuncSetAttribute(attn_kernel, cudaFuncAttributeMaxDynamicSharedMemorySize,
                         ATT_SMEM_BYTES);

    preround_x<<<2048, 256>>>((const float4*)x);                         // idx 0
    preround_w<<<1024, 256>>>((const float4*)Wq, (const float4*)Wk,
                              (const float4*)Wv);                        // idx 1
    dim3 g1(OUTCH * 2 / 128, (NB * NTOK) / 128);
    qkv_gemm<<<g1, 256, GEMM_SMEM_BYTES>>>(bq, bk, bv);                  // idx 2
    dim3 g2(NTOK / 64, NB * NH);
    attn_kernel<<<g2, 128, ATT_SMEM_BYTES>>>(out);                       // idx 3 -> profiled
}